// round 3
// baseline (speedup 1.0000x reference)
#include <cuda_runtime.h>
#include <cuda_bf16.h>
#include <cstddef>

#define NN 4096
#define CAP 192

// ---------------- device scratch ----------------
__device__ float g_h [NN*64];
__device__ float g_t1[NN*64];
__device__ float g_t2[NN*64];
__device__ float g_A2[NN*64];
__device__ float g_B2[NN*64];
__device__ float g_Wca[64*64];
__device__ float g_Wcb[64*64];
__device__ float g_c2[64];
__device__ int   g_cnt[NN];
__device__ int   g_col[NN*CAP];
__device__ unsigned g_arrive;

// ---------------- grid-wide barrier (monotonic counter, reset by host memset) ----------------
__device__ __forceinline__ void gsync(unsigned target)
{
    __threadfence();                 // release: make this thread's writes visible
    __syncthreads();
    if (threadIdx.x == 0) {
        atomicAdd(&g_arrive, 1u);
        while (atomicAdd(&g_arrive, 0u) < target) {}
    }
    __syncthreads();
    __threadfence();                 // acquire: invalidate L1 before reading others' data
}

// ---------------- stage helpers ----------------
__device__ __forceinline__ void st_gemm_dual(const float* __restrict__ X,
    const float* __restrict__ Wa, const float* __restrict__ ba,
    const float* __restrict__ Wb, const float* __restrict__ bb,
    float* __restrict__ Ya, float* __restrict__ Yb,
    int G, float (*sW)[4096], float (*sx)[64])
{
    for (int idx = threadIdx.x; idx < 4096; idx += 256) {
        sW[0][idx] = Wa[idx];
        sW[1][idx] = Wb[idx];
    }
    __syncthreads();
    const int j = threadIdx.x & 63, rg = threadIdx.x >> 6;
    const float bva = ba ? ba[j] : 0.f;
    const float bvb = bb ? bb[j] : 0.f;
    for (int tile = blockIdx.x; tile < 1024; tile += G) {
        const int row = tile*4 + rg;
        __syncthreads();
        sx[rg][j] = X[row*64 + j];
        __syncthreads();
        float a0 = bva, a1 = bvb;
#pragma unroll
        for (int k = 0; k < 64; k++) {
            const float xv = sx[rg][k];
            a0 = fmaf(xv, sW[0][k*64 + j], a0);
            a1 = fmaf(xv, sW[1][k*64 + j], a1);
        }
        Ya[row*64 + j] = a0;
        Yb[row*64 + j] = a1;
    }
}

// in-place residual: h[row] = h[row] + relu(h[row]@W + b)
__device__ __forceinline__ void st_gemm_res(float* __restrict__ H,
    const float* __restrict__ W, const float* __restrict__ bias,
    int G, float* sW, float (*sx)[64])
{
    for (int idx = threadIdx.x; idx < 4096; idx += 256) sW[idx] = W[idx];
    __syncthreads();
    const int j = threadIdx.x & 63, rg = threadIdx.x >> 6;
    const float bj = bias[j];
    for (int tile = blockIdx.x; tile < 1024; tile += G) {
        const int row = tile*4 + rg;
        __syncthreads();
        sx[rg][j] = H[row*64 + j];
        __syncthreads();
        float acc = bj;
#pragma unroll
        for (int k = 0; k < 64; k++) acc = fmaf(sx[rg][k], sW[k*64 + j], acc);
        H[row*64 + j] = sx[rg][j] + fmaxf(acc, 0.f);
    }
}

__device__ __forceinline__ void st_gat(const float* __restrict__ gl,
    const float* __restrict__ gr, const float* __restrict__ att,
    const float* __restrict__ cb, float* __restrict__ h, int G)
{
    const int lane = threadIdx.x & 31;
    const int c = lane*2;
    const float2 av = *(const float2*)(att + c);
    const float2 cbv = *(const float2*)(cb + c);
    for (int i = blockIdx.x*8 + (threadIdx.x >> 5); i < NN; i += G*8) {
        const float2 grv = *(const float2*)(gr + i*64 + c);
        float m = -3.0e38f, den = 0.f, v0 = 0.f, v1 = 0.f;
        const int cnt  = min(g_cnt[i], CAP);
        const int base = i*CAP;
        int p = 0;
        for (; p + 2 <= cnt; p += 2) {
            const int j0 = g_col[base + p];
            const int j1 = g_col[base + p + 1];
            const float2 ga = *(const float2*)(gl + j0*64 + c);
            const float2 gb = *(const float2*)(gl + j1*64 + c);
            float sx0 = ga.x + grv.x, sy0 = ga.y + grv.y;
            sx0 = sx0 > 0.f ? sx0 : 0.2f*sx0;  sy0 = sy0 > 0.f ? sy0 : 0.2f*sy0;
            float e0 = sx0*av.x + sy0*av.y;
            float tx = gb.x + grv.x, ty = gb.y + grv.y;
            tx = tx > 0.f ? tx : 0.2f*tx;  ty = ty > 0.f ? ty : 0.2f*ty;
            float e1 = tx*av.x + ty*av.y;
            e0 += __shfl_xor_sync(0xffffffffu, e0, 1);
            e1 += __shfl_xor_sync(0xffffffffu, e1, 1);
            e0 += __shfl_xor_sync(0xffffffffu, e0, 2);
            e1 += __shfl_xor_sync(0xffffffffu, e1, 2);
            e0 += __shfl_xor_sync(0xffffffffu, e0, 4);
            e1 += __shfl_xor_sync(0xffffffffu, e1, 4);
            {
                const float mn = fmaxf(m, e0);
                const float wE = __expf(e0 - mn), wM = __expf(m - mn);
                den = den*wM + wE;  v0 = v0*wM + wE*ga.x;  v1 = v1*wM + wE*ga.y;
                m = mn;
            }
            {
                const float mn = fmaxf(m, e1);
                const float wE = __expf(e1 - mn), wM = __expf(m - mn);
                den = den*wM + wE;  v0 = v0*wM + wE*gb.x;  v1 = v1*wM + wE*gb.y;
                m = mn;
            }
        }
        if (p < cnt) {
            const int j0 = g_col[base + p];
            const float2 ga = *(const float2*)(gl + j0*64 + c);
            float sx0 = ga.x + grv.x, sy0 = ga.y + grv.y;
            sx0 = sx0 > 0.f ? sx0 : 0.2f*sx0;  sy0 = sy0 > 0.f ? sy0 : 0.2f*sy0;
            float e0 = sx0*av.x + sy0*av.y;
            e0 += __shfl_xor_sync(0xffffffffu, e0, 1);
            e0 += __shfl_xor_sync(0xffffffffu, e0, 2);
            e0 += __shfl_xor_sync(0xffffffffu, e0, 4);
            const float mn = fmaxf(m, e0);
            const float wE = __expf(e0 - mn), wM = __expf(m - mn);
            den = den*wM + wE;  v0 = v0*wM + wE*ga.x;  v1 = v1*wM + wE*ga.y;
            m = mn;
        }
        const float inv = 1.f/den;
        float2* hp = (float2*)(h + i*64 + c);
        float2 hv = *hp;
        hv.x += v0*inv + cbv.x;
        hv.y += v1*inv + cbv.y;
        *hp = hv;
    }
}

__device__ __forceinline__ void st_edge(const float* __restrict__ We3,
    const float* __restrict__ be3, float* __restrict__ out, int G)
{
    const int lane = threadIdx.x & 31;
    const int c = lane*2;
    const float2 cc = *(const float2*)(g_c2 + c);
    const float2 w3 = *(const float2*)(We3 + c);
    const float  b3 = be3[0];
    for (int i = blockIdx.x*8 + (threadIdx.x >> 5); i < NN; i += G*8) {
        const float2 bv = *(const float2*)(g_B2 + i*64 + c);
        const float2 k0 = make_float2(bv.x + cc.x, bv.y + cc.y);
        const int cnt  = min(g_cnt[i], CAP);
        const int base = i*CAP;
        int t = 1;                               // slot 0 = self-loop
        for (; t + 2 <= cnt; t += 2) {
            const int s0 = g_col[base + t];
            const int s1 = g_col[base + t + 1];
            const float2 a0 = *(const float2*)(g_A2 + s0*64 + c);
            const float2 a1 = *(const float2*)(g_A2 + s1*64 + c);
            float x0 = fmaxf(a0.x + k0.x, 0.f), y0 = fmaxf(a0.y + k0.y, 0.f);
            float x1 = fmaxf(a1.x + k0.x, 0.f), y1 = fmaxf(a1.y + k0.y, 0.f);
            float p0 = x0*w3.x + y0*w3.y;
            float p1 = x1*w3.x + y1*w3.y;
#pragma unroll
            for (int off = 16; off; off >>= 1) {
                p0 += __shfl_xor_sync(0xffffffffu, p0, off);
                p1 += __shfl_xor_sync(0xffffffffu, p1, off);
            }
            if (lane == 0) {
                out[(size_t)s0*NN + i] = 1.f/(1.f + __expf(-(p0 + b3)));
                out[(size_t)s1*NN + i] = 1.f/(1.f + __expf(-(p1 + b3)));
            }
        }
        if (t < cnt) {
            const int s0 = g_col[base + t];
            const float2 a0 = *(const float2*)(g_A2 + s0*64 + c);
            float x0 = fmaxf(a0.x + k0.x, 0.f), y0 = fmaxf(a0.y + k0.y, 0.f);
            float p0 = x0*w3.x + y0*w3.y;
#pragma unroll
            for (int off = 16; off; off >>= 1) p0 += __shfl_xor_sync(0xffffffffu, p0, off);
            if (lane == 0) out[(size_t)s0*NN + i] = 1.f/(1.f + __expf(-(p0 + b3)));
        }
    }
}

// ---------------- the mega kernel ----------------
__global__ void __launch_bounds__(256, 4)
k_mega(const float* __restrict__ x,
       const int* __restrict__ src, const int* __restrict__ dst,
       const float* __restrict__ W1,  const float* __restrict__ b1,
       const float* __restrict__ W2,  const float* __restrict__ b2,
       const float* __restrict__ Wl1, const float* __restrict__ bl1,
       const float* __restrict__ Wr1, const float* __restrict__ br1,
       const float* __restrict__ att1,const float* __restrict__ cb1,
       const float* __restrict__ W4,  const float* __restrict__ b4,
       const float* __restrict__ Wl2, const float* __restrict__ bl2,
       const float* __restrict__ Wr2, const float* __restrict__ br2,
       const float* __restrict__ att2,const float* __restrict__ cb2,
       const float* __restrict__ W5,  const float* __restrict__ b5,
       const float* __restrict__ We1, const float* __restrict__ be1,
       const float* __restrict__ We2, const float* __restrict__ be2,
       const float* __restrict__ We3, const float* __restrict__ be3,
       float* __restrict__ out, int E, int G)
{
    __shared__ float sW[2][4096];
    __shared__ float sx[4][64];
    __shared__ float sxin[4][16];

    const int bid = blockIdx.x;
    const int tid = threadIdx.x;
    unsigned tgt = (unsigned)G;

    // ================= Stage 0: encoder | fold | csr-init | zero-out =================
    if (bid < 64) {
        // encoder: h = relu(x@W1+b1); h += relu(h@W2+b2)
        const int j  = tid & 63;
        const int rg = tid >> 6;
        for (int idx = tid; idx < 1024; idx += 256) sW[0][idx] = W1[idx];
        for (int idx = tid; idx < 4096; idx += 256) sW[1][idx] = W2[idx];
        __syncthreads();
        const float b1j = b1[j], b2j = b2[j];
        for (int tile = bid; tile < 1024; tile += 64) {
            const int row = tile*4 + rg;
            __syncthreads();
            if (j < 16) sxin[rg][j] = x[row*16 + j];
            __syncthreads();
            float acc = b1j;
#pragma unroll
            for (int k = 0; k < 16; k++) acc = fmaf(sxin[rg][k], sW[0][k*64 + j], acc);
            const float h1 = fmaxf(acc, 0.f);
            sx[rg][j] = h1;
            __syncthreads();
            float acc2 = b2j;
#pragma unroll
            for (int k = 0; k < 64; k++) acc2 = fmaf(sx[rg][k], sW[1][k*64 + j], acc2);
            g_h[row*64 + j] = h1 + fmaxf(acc2, 0.f);
        }
    } else if (bid < 72) {
        // fold: Wca = We1[:64]@We2, Wcb = We1[64:]@We2, c2 = be1@We2+be2
        const int fb = bid - 64;
#pragma unroll
        for (int t = 0; t < 2; t++) {
            const int idx = fb*512 + t*256 + tid;
            const int i = idx >> 6, j = idx & 63;
            float sa = 0.f, sb = 0.f;
            for (int m = 0; m < 64; m++) {
                const float w2 = We2[m*64 + j];
                sa = fmaf(We1[i*64 + m],      w2, sa);
                sb = fmaf(We1[(64+i)*64 + m], w2, sb);
            }
            g_Wca[idx] = sa;
            g_Wcb[idx] = sb;
        }
        if (fb == 0 && tid < 64) {
            float cc = be2[tid];
            for (int m = 0; m < 64; m++) cc = fmaf(be1[m], We2[m*64 + tid], cc);
            g_c2[tid] = cc;
        }
    } else if (bid < 88) {
        const int i = (bid - 72)*256 + tid;
        if (i < NN) { g_cnt[i] = 1; g_col[i*CAP] = i; }
    } else {
        // zero 4096x4096 output
        const int zb = bid - 88;
        const long ZT = (long)(G - 88) * 256;
        float4 z4 = make_float4(0.f, 0.f, 0.f, 0.f);
        float4* o4 = (float4*)out;
        for (long idx = (long)zb*256 + tid; idx < 4194304L; idx += ZT) o4[idx] = z4;
    }
    gsync(tgt); tgt += G;

    // ================= Stage 1: bucket fill =================
    for (int e = bid*256 + tid; e < E; e += G*256) {
        const int d = dst[e];
        const int p = atomicAdd(&g_cnt[d], 1);
        if (p < CAP) g_col[d*CAP + p] = src[e];
    }
    gsync(tgt); tgt += G;

    // ================= GAT layer 1 =================
    st_gemm_dual(g_h, Wl1, bl1, Wr1, br1, g_t1, g_t2, G, sW, sx);
    gsync(tgt); tgt += G;
    st_gat(g_t1, g_t2, att1, cb1, g_h, G);
    gsync(tgt); tgt += G;
    st_gemm_res(g_h, W4, b4, G, sW[0], sx);
    gsync(tgt); tgt += G;

    // ================= GAT layer 2 =================
    st_gemm_dual(g_h, Wl2, bl2, Wr2, br2, g_t1, g_t2, G, sW, sx);
    gsync(tgt); tgt += G;
    st_gat(g_t1, g_t2, att2, cb2, g_h, G);
    gsync(tgt); tgt += G;
    st_gemm_res(g_h, W5, b5, G, sW[0], sx);
    gsync(tgt); tgt += G;

    // ================= edge MLP =================
    st_gemm_dual(g_h, g_Wca, nullptr, g_Wcb, nullptr, g_A2, g_B2, G, sW, sx);
    gsync(tgt); tgt += G;
    st_edge(We3, be3, out, G);
}

// ---------------- launch ----------------
extern "C" void kernel_launch(void* const* d_in, const int* in_sizes, int n_in,
                              void* d_out, int out_size)
{
    const float* x    = (const float*)d_in[0];
    const int*   src  = (const int*)  d_in[2];
    const int*   dst  = (const int*)  d_in[3];
    const float* W1   = (const float*)d_in[4];
    const float* b1   = (const float*)d_in[5];
    const float* W2   = (const float*)d_in[6];
    const float* b2   = (const float*)d_in[7];
    const float* Wl1  = (const float*)d_in[8];
    const float* bl1  = (const float*)d_in[9];
    const float* Wr1  = (const float*)d_in[10];
    const float* br1  = (const float*)d_in[11];
    const float* att1 = (const float*)d_in[12];
    const float* cb1  = (const float*)d_in[13];
    const float* W4   = (const float*)d_in[14];
    const float* b4   = (const float*)d_in[15];
    const float* Wl2  = (const float*)d_in[16];
    const float* bl2  = (const float*)d_in[17];
    const float* Wr2  = (const float*)d_in[18];
    const float* br2  = (const float*)d_in[19];
    const float* att2 = (const float*)d_in[20];
    const float* cb2  = (const float*)d_in[21];
    const float* W5   = (const float*)d_in[22];
    const float* b5   = (const float*)d_in[23];
    const float* We1  = (const float*)d_in[24];
    const float* be1  = (const float*)d_in[25];
    const float* We2  = (const float*)d_in[26];
    const float* be2  = (const float*)d_in[27];
    const float* We3  = (const float*)d_in[28];
    const float* be3  = (const float*)d_in[29];
    const int E = in_sizes[2];

    int sms = 148;
    cudaDeviceGetAttribute(&sms, cudaDevAttrMultiProcessorCount, 0);
    const int G = sms * 4;

    void* pa;
    cudaGetSymbolAddress(&pa, g_arrive);
    cudaMemsetAsync(pa, 0, sizeof(unsigned), 0);

    k_mega<<<G, 256>>>(x, src, dst, W1, b1, W2, b2,
                       Wl1, bl1, Wr1, br1, att1, cb1, W4, b4,
                       Wl2, bl2, Wr2, br2, att2, cb2, W5, b5,
                       We1, be1, We2, be2, We3, be3,
                       (float*)d_out, E, G);
}

// round 4
// speedup vs baseline: 1.1518x; 1.1518x over previous
#include <cuda_runtime.h>
#include <cuda_bf16.h>
#include <cstddef>

#define NN 4096
#define CAP 192

// ---------------- device scratch ----------------
__device__ float g_h [NN*64];
__device__ float g_t1[NN*64];   // gl layer1
__device__ float g_t2[NN*64];   // gr layer1
__device__ float g_t3[NN*64];   // gl layer2
__device__ float g_t4[NN*64];   // gr layer2
__device__ float g_A2[NN*64];
__device__ float g_B2[NN*64];
__device__ float g_Wca[64*64];
__device__ float g_Wcb[64*64];
__device__ float g_c2[64];
__device__ float g_zero64[64];  // stays zero (zero-initialized)
__device__ int   g_cnt[NN];
__device__ int   g_col[NN*CAP];

// =====================================================================
// K1: encoder(+gl1/gr1) | We-fold | bucket fill | zero output
// =====================================================================
__global__ void __launch_bounds__(256, 4)
k_prep(const float* __restrict__ x, const int* __restrict__ src, const int* __restrict__ dst,
       const float* __restrict__ W1,  const float* __restrict__ b1,
       const float* __restrict__ W2,  const float* __restrict__ b2,
       const float* __restrict__ Wl1, const float* __restrict__ bl1,
       const float* __restrict__ Wr1, const float* __restrict__ br1,
       const float* __restrict__ We1, const float* __restrict__ be1,
       const float* __restrict__ We2, const float* __restrict__ be2,
       float* __restrict__ out, int E)
{
    __shared__ float spool[4096];       // fold: We2 ; encoder: 8 per-warp rows (512 floats)
    const int bid = blockIdx.x, tid = threadIdx.x;
    const int w = tid >> 5, lane = tid & 31;

    if (bid < 96) {
        // ---------- encoder: h=relu(xW1+b1); h+=relu(hW2+b2); gl1=hWl1+bl1; gr1=hWr1+br1 ----------
        float* row = spool + w*64;
        const int c = lane*2;
        const float2 b1v  = *(const float2*)&b1[c];
        const float2 b2v  = *(const float2*)&b2[c];
        const float2 blv  = *(const float2*)&bl1[c];
        const float2 brv  = *(const float2*)&br1[c];
        for (int r = bid*8 + w; r < NN; r += 96*8) {
            const float xv = x[r*16 + (lane & 15)];
            float a0 = b1v.x, a1 = b1v.y;
#pragma unroll
            for (int k = 0; k < 16; k++) {
                const float xk = __shfl_sync(0xffffffffu, xv, k);
                const float2 wv = *(const float2*)&W1[k*64 + c];
                a0 = fmaf(xk, wv.x, a0);  a1 = fmaf(xk, wv.y, a1);
            }
            float h0 = fmaxf(a0, 0.f), h1 = fmaxf(a1, 0.f);
            row[c] = h0;  row[c+1] = h1;
            __syncwarp();
            float c0 = b2v.x, c1 = b2v.y;
#pragma unroll
            for (int k = 0; k < 64; k++) {
                const float rk = row[k];
                const float2 wv = *(const float2*)&W2[k*64 + c];
                c0 = fmaf(rk, wv.x, c0);  c1 = fmaf(rk, wv.y, c1);
            }
            h0 += fmaxf(c0, 0.f);  h1 += fmaxf(c1, 0.f);
            *(float2*)&g_h[r*64 + c] = make_float2(h0, h1);
            __syncwarp();
            row[c] = h0;  row[c+1] = h1;
            __syncwarp();
            float l0 = blv.x, l1 = blv.y, r0 = brv.x, r1 = brv.y;
#pragma unroll
            for (int k = 0; k < 64; k++) {
                const float rk = row[k];
                const float2 wl = *(const float2*)&Wl1[k*64 + c];
                const float2 wr = *(const float2*)&Wr1[k*64 + c];
                l0 = fmaf(rk, wl.x, l0);  l1 = fmaf(rk, wl.y, l1);
                r0 = fmaf(rk, wr.x, r0);  r1 = fmaf(rk, wr.y, r1);
            }
            *(float2*)&g_t1[r*64 + c] = make_float2(l0, l1);
            *(float2*)&g_t2[r*64 + c] = make_float2(r0, r1);
            __syncwarp();
        }
    } else if (bid < 98) {
        // ---------- fold: Wca=We1[:64]@We2, Wcb=We1[64:]@We2, c2=be1@We2+be2 ----------
        const int fb = bid - 96;
        for (int idx = tid; idx < 4096; idx += 256) spool[idx] = We2[idx];
        __syncthreads();
        const int j = tid & 63, il = tid >> 6;
        for (int pass = 0; pass < 8; pass++) {
            const int i = fb*32 + pass*4 + il;
            float sa = 0.f, sb = 0.f;
#pragma unroll
            for (int m = 0; m < 64; m++) {
                const float w2 = spool[m*64 + j];
                sa = fmaf(We1[i*64 + m],      w2, sa);
                sb = fmaf(We1[(64+i)*64 + m], w2, sb);
            }
            g_Wca[i*64 + j] = sa;
            g_Wcb[i*64 + j] = sb;
        }
        if (fb == 0 && tid < 64) {
            float cc = be2[tid];
            for (int m = 0; m < 64; m++) cc = fmaf(be1[m], spool[m*64 + tid], cc);
            g_c2[tid] = cc;
        }
    } else if (bid < 146) {
        // ---------- bucket fill (g_cnt pre-zeroed by memset; self-loops implicit) ----------
        for (int e = (bid - 98)*256 + tid; e < E; e += 48*256) {
            const int d = dst[e];
            const int p = atomicAdd(&g_cnt[d], 1);
            if (p < CAP) g_col[d*CAP + p] = src[e];
        }
    } else {
        // ---------- zero 64MB output ----------
        const long ZB = (long)(gridDim.x - 146) * 256;
        float4* o4 = (float4*)out;
        const float4 z4 = make_float4(0.f, 0.f, 0.f, 0.f);
        for (long idx = (long)(bid - 146)*256 + tid; idx < 4194304L; idx += ZB) o4[idx] = z4;
    }
}

// =====================================================================
// K2/K3: fused GAT + residual GEMM + two row-local output GEMMs
//   H[i] += attn(i) + cb;  H[i] += relu(H[i]@Wres + bres);
//   O1[i] = H[i]@Wo1 + bo1;  O2[i] = H[i]@Wo2 + bo2
// =====================================================================
__global__ void __launch_bounds__(256, 4)
k_gatres(const float* __restrict__ gl, const float* __restrict__ gr,
         const float* __restrict__ att, const float* __restrict__ cb,
         const float* __restrict__ Wres, const float* __restrict__ bres,
         const float* __restrict__ Wo1,  const float* __restrict__ bo1, float* __restrict__ O1,
         const float* __restrict__ Wo2,  const float* __restrict__ bo2, float* __restrict__ O2,
         float* __restrict__ H)
{
    __shared__ float rows[8][64];
    const int w = threadIdx.x >> 5, lane = threadIdx.x & 31;
    const int i = blockIdx.x*8 + w;
    const int c = lane*2;
    float* row = rows[w];

    const float2 av  = *(const float2*)&att[c];
    const float2 grv = *(const float2*)&gr[i*64 + c];

    // self-loop first (always present)
    const float2 gs = *(const float2*)&gl[i*64 + c];
    float m, den, v0, v1;
    {
        float sx = gs.x + grv.x, sy = gs.y + grv.y;
        sx = sx > 0.f ? sx : 0.2f*sx;  sy = sy > 0.f ? sy : 0.2f*sy;
        float e = sx*av.x + sy*av.y;
        e += __shfl_xor_sync(0xffffffffu, e, 1);
        e += __shfl_xor_sync(0xffffffffu, e, 2);
        e += __shfl_xor_sync(0xffffffffu, e, 4);
        m = e;  den = 1.f;  v0 = gs.x;  v1 = gs.y;
    }
    // real incoming edges
    const int cnt  = min(g_cnt[i], CAP);
    const int base = i*CAP;
    int p = 0;
    for (; p + 2 <= cnt; p += 2) {
        const int j0 = g_col[base + p];
        const int j1 = g_col[base + p + 1];
        const float2 ga = *(const float2*)&gl[j0*64 + c];
        const float2 gb = *(const float2*)&gl[j1*64 + c];
        float sx0 = ga.x + grv.x, sy0 = ga.y + grv.y;
        sx0 = sx0 > 0.f ? sx0 : 0.2f*sx0;  sy0 = sy0 > 0.f ? sy0 : 0.2f*sy0;
        float e0 = sx0*av.x + sy0*av.y;
        float tx = gb.x + grv.x, ty = gb.y + grv.y;
        tx = tx > 0.f ? tx : 0.2f*tx;  ty = ty > 0.f ? ty : 0.2f*ty;
        float e1 = tx*av.x + ty*av.y;
        e0 += __shfl_xor_sync(0xffffffffu, e0, 1);
        e1 += __shfl_xor_sync(0xffffffffu, e1, 1);
        e0 += __shfl_xor_sync(0xffffffffu, e0, 2);
        e1 += __shfl_xor_sync(0xffffffffu, e1, 2);
        e0 += __shfl_xor_sync(0xffffffffu, e0, 4);
        e1 += __shfl_xor_sync(0xffffffffu, e1, 4);
        {
            const float mn = fmaxf(m, e0);
            const float wE = __expf(e0 - mn), wM = __expf(m - mn);
            den = den*wM + wE;  v0 = v0*wM + wE*ga.x;  v1 = v1*wM + wE*ga.y;
            m = mn;
        }
        {
            const float mn = fmaxf(m, e1);
            const float wE = __expf(e1 - mn), wM = __expf(m - mn);
            den = den*wM + wE;  v0 = v0*wM + wE*gb.x;  v1 = v1*wM + wE*gb.y;
            m = mn;
        }
    }
    if (p < cnt) {
        const int j0 = g_col[base + p];
        const float2 ga = *(const float2*)&gl[j0*64 + c];
        float sx0 = ga.x + grv.x, sy0 = ga.y + grv.y;
        sx0 = sx0 > 0.f ? sx0 : 0.2f*sx0;  sy0 = sy0 > 0.f ? sy0 : 0.2f*sy0;
        float e0 = sx0*av.x + sy0*av.y;
        e0 += __shfl_xor_sync(0xffffffffu, e0, 1);
        e0 += __shfl_xor_sync(0xffffffffu, e0, 2);
        e0 += __shfl_xor_sync(0xffffffffu, e0, 4);
        const float mn = fmaxf(m, e0);
        const float wE = __expf(e0 - mn), wM = __expf(m - mn);
        den = den*wM + wE;  v0 = v0*wM + wE*ga.x;  v1 = v1*wM + wE*ga.y;
        m = mn;
    }
    const float inv = 1.f/den;
    const float2 cbv  = *(const float2*)&cb[c];
    const float2 hold = *(const float2*)&H[i*64 + c];
    float h0 = hold.x + v0*inv + cbv.x;
    float h1 = hold.y + v1*inv + cbv.y;

    // residual GEMM
    row[c] = h0;  row[c+1] = h1;
    __syncwarp();
    {
        const float2 bv = *(const float2*)&bres[c];
        float a0 = bv.x, a1 = bv.y;
#pragma unroll
        for (int k = 0; k < 64; k++) {
            const float rk = row[k];
            const float2 wv = *(const float2*)&Wres[k*64 + c];
            a0 = fmaf(rk, wv.x, a0);  a1 = fmaf(rk, wv.y, a1);
        }
        h0 += fmaxf(a0, 0.f);  h1 += fmaxf(a1, 0.f);
    }
    *(float2*)&H[i*64 + c] = make_float2(h0, h1);
    __syncwarp();
    row[c] = h0;  row[c+1] = h1;
    __syncwarp();

    // two row-local output GEMMs
    {
        const float2 b1v = *(const float2*)&bo1[c];
        const float2 b2v = *(const float2*)&bo2[c];
        float a0 = b1v.x, a1 = b1v.y, a2 = b2v.x, a3 = b2v.y;
#pragma unroll
        for (int k = 0; k < 64; k++) {
            const float rk = row[k];
            const float2 w1 = *(const float2*)&Wo1[k*64 + c];
            const float2 w2 = *(const float2*)&Wo2[k*64 + c];
            a0 = fmaf(rk, w1.x, a0);  a1 = fmaf(rk, w1.y, a1);
            a2 = fmaf(rk, w2.x, a2);  a3 = fmaf(rk, w2.y, a3);
        }
        *(float2*)&O1[i*64 + c] = make_float2(a0, a1);
        *(float2*)&O2[i*64 + c] = make_float2(a2, a3);
    }
    __syncwarp();
}

// =====================================================================
// K4: edge MLP — warp per dst node over its bucket
// =====================================================================
__global__ void __launch_bounds__(256, 4)
k_edge(const float* __restrict__ We3, const float* __restrict__ be3, float* __restrict__ out)
{
    const int w = threadIdx.x >> 5, lane = threadIdx.x & 31;
    const int i = blockIdx.x*8 + w;
    const int c = lane*2;
    const float2 cc = *(const float2*)&g_c2[c];
    const float2 w3 = *(const float2*)&We3[c];
    const float  b3 = be3[0];
    const float2 bv = *(const float2*)&g_B2[i*64 + c];
    const float2 k0 = make_float2(bv.x + cc.x, bv.y + cc.y);
    const int cnt  = min(g_cnt[i], CAP);
    const int base = i*CAP;
    int t = 0;
    for (; t + 2 <= cnt; t += 2) {
        const int s0 = g_col[base + t];
        const int s1 = g_col[base + t + 1];
        const float2 a0 = *(const float2*)&g_A2[s0*64 + c];
        const float2 a1 = *(const float2*)&g_A2[s1*64 + c];
        float x0 = fmaxf(a0.x + k0.x, 0.f), y0 = fmaxf(a0.y + k0.y, 0.f);
        float x1 = fmaxf(a1.x + k0.x, 0.f), y1 = fmaxf(a1.y + k0.y, 0.f);
        float p0 = x0*w3.x + y0*w3.y;
        float p1 = x1*w3.x + y1*w3.y;
#pragma unroll
        for (int off = 16; off; off >>= 1) {
            p0 += __shfl_xor_sync(0xffffffffu, p0, off);
            p1 += __shfl_xor_sync(0xffffffffu, p1, off);
        }
        if (lane == 0) {
            out[(size_t)s0*NN + i] = 1.f/(1.f + __expf(-(p0 + b3)));
            out[(size_t)s1*NN + i] = 1.f/(1.f + __expf(-(p1 + b3)));
        }
    }
    if (t < cnt) {
        const int s0 = g_col[base + t];
        const float2 a0 = *(const float2*)&g_A2[s0*64 + c];
        float x0 = fmaxf(a0.x + k0.x, 0.f), y0 = fmaxf(a0.y + k0.y, 0.f);
        float p0 = x0*w3.x + y0*w3.y;
#pragma unroll
        for (int off = 16; off; off >>= 1) p0 += __shfl_xor_sync(0xffffffffu, p0, off);
        if (lane == 0) out[(size_t)s0*NN + i] = 1.f/(1.f + __expf(-(p0 + b3)));
    }
}

// ---------------- launch ----------------
extern "C" void kernel_launch(void* const* d_in, const int* in_sizes, int n_in,
                              void* d_out, int out_size)
{
    const float* x    = (const float*)d_in[0];
    const int*   src  = (const int*)  d_in[2];
    const int*   dst  = (const int*)  d_in[3];
    const float* W1   = (const float*)d_in[4];
    const float* b1   = (const float*)d_in[5];
    const float* W2   = (const float*)d_in[6];
    const float* b2   = (const float*)d_in[7];
    const float* Wl1  = (const float*)d_in[8];
    const float* bl1  = (const float*)d_in[9];
    const float* Wr1  = (const float*)d_in[10];
    const float* br1  = (const float*)d_in[11];
    const float* att1 = (const float*)d_in[12];
    const float* cb1  = (const float*)d_in[13];
    const float* W4   = (const float*)d_in[14];
    const float* b4   = (const float*)d_in[15];
    const float* Wl2  = (const float*)d_in[16];
    const float* bl2  = (const float*)d_in[17];
    const float* Wr2  = (const float*)d_in[18];
    const float* br2  = (const float*)d_in[19];
    const float* att2 = (const float*)d_in[20];
    const float* cb2  = (const float*)d_in[21];
    const float* W5   = (const float*)d_in[22];
    const float* b5   = (const float*)d_in[23];
    const float* We1  = (const float*)d_in[24];
    const float* be1  = (const float*)d_in[25];
    const float* We2  = (const float*)d_in[26];
    const float* be2  = (const float*)d_in[27];
    const float* We3  = (const float*)d_in[28];
    const float* be3  = (const float*)d_in[29];
    const int E = in_sizes[2];

    int sms = 148;
    cudaDeviceGetAttribute(&sms, cudaDevAttrMultiProcessorCount, 0);
    const int G1 = sms * 4;

    void* p;
    cudaGetSymbolAddress(&p, g_cnt);
    cudaMemsetAsync(p, 0, NN*sizeof(int), 0);

    float *pt1, *pt2, *pt3, *pt4, *pA2, *pB2, *pWca, *pWcb, *pz, *ph;
    cudaGetSymbolAddress(&p, g_t1);  pt1 = (float*)p;
    cudaGetSymbolAddress(&p, g_t2);  pt2 = (float*)p;
    cudaGetSymbolAddress(&p, g_t3);  pt3 = (float*)p;
    cudaGetSymbolAddress(&p, g_t4);  pt4 = (float*)p;
    cudaGetSymbolAddress(&p, g_A2);  pA2 = (float*)p;
    cudaGetSymbolAddress(&p, g_B2);  pB2 = (float*)p;
    cudaGetSymbolAddress(&p, g_Wca); pWca = (float*)p;
    cudaGetSymbolAddress(&p, g_Wcb); pWcb = (float*)p;
    cudaGetSymbolAddress(&p, g_zero64); pz = (float*)p;
    cudaGetSymbolAddress(&p, g_h);   ph = (float*)p;

    k_prep<<<G1, 256>>>(x, src, dst, W1, b1, W2, b2, Wl1, bl1, Wr1, br1,
                        We1, be1, We2, be2, (float*)d_out, E);

    // GAT1 + W4 residual + gl2/gr2 projection
    k_gatres<<<512, 256>>>(pt1, pt2, att1, cb1, W4, b4,
                           Wl2, bl2, pt3,  Wr2, br2, pt4,  ph);

    // GAT2 + W5 residual + A2/B2 projection
    k_gatres<<<512, 256>>>(pt3, pt4, att2, cb2, W5, b5,
                           pWca, pz, pA2,  pWcb, pz, pB2,  ph);

    k_edge<<<512, 256>>>(We3, be3, (float*)d_out);
}

// round 5
// speedup vs baseline: 1.2364x; 1.0735x over previous
#include <cuda_runtime.h>
#include <cuda_bf16.h>
#include <cstddef>

#define NN 4096
#define CAP 192

// ---------------- device scratch ----------------
__device__ float g_h [NN*64];
__device__ float g_t1[NN*64];   // gl layer1
__device__ float g_t2[NN*64];   // gr layer1
__device__ float g_t3[NN*64];   // gl layer2
__device__ float g_t4[NN*64];   // gr layer2
__device__ float g_A2[NN*64];
__device__ float g_B2[NN*64];
__device__ float g_Wca[64*64];
__device__ float g_Wcb[64*64];
__device__ float g_c2[64];
__device__ float g_zero64[64];  // stays zero
__device__ int   g_cnt[NN];
__device__ int   g_col[NN*CAP];

// =====================================================================
// K1: encoder(+gl1/gr1) | We-fold | bucket fill | zero output
// =====================================================================
__global__ void __launch_bounds__(256, 4)
k_prep(const float* __restrict__ x, const int* __restrict__ src, const int* __restrict__ dst,
       const float* __restrict__ W1,  const float* __restrict__ b1,
       const float* __restrict__ W2,  const float* __restrict__ b2,
       const float* __restrict__ Wl1, const float* __restrict__ bl1,
       const float* __restrict__ Wr1, const float* __restrict__ br1,
       const float* __restrict__ We1, const float* __restrict__ be1,
       const float* __restrict__ We2, const float* __restrict__ be2,
       float* __restrict__ out, int E)
{
    __shared__ float spool[4096];
    const int bid = blockIdx.x, tid = threadIdx.x;
    const int w = tid >> 5, lane = tid & 31;

    if (bid < 160) {
        // ---------- encoder: h=relu(xW1+b1); h+=relu(hW2+b2); gl1/gr1 ----------
        float* row = spool + w*64;
        const int c = lane*2;
        const float2 b1v  = *(const float2*)&b1[c];
        const float2 b2v  = *(const float2*)&b2[c];
        const float2 blv  = *(const float2*)&bl1[c];
        const float2 brv  = *(const float2*)&br1[c];
        for (int r = bid*8 + w; r < NN; r += 160*8) {
            const float xv = x[r*16 + (lane & 15)];
            float a0 = b1v.x, a1 = b1v.y;
#pragma unroll
            for (int k = 0; k < 16; k++) {
                const float xk = __shfl_sync(0xffffffffu, xv, k);
                const float2 wv = *(const float2*)&W1[k*64 + c];
                a0 = fmaf(xk, wv.x, a0);  a1 = fmaf(xk, wv.y, a1);
            }
            float h0 = fmaxf(a0, 0.f), h1 = fmaxf(a1, 0.f);
            row[c] = h0;  row[c+1] = h1;
            __syncwarp();
            float c0 = b2v.x, c1 = b2v.y;
#pragma unroll
            for (int k = 0; k < 64; k++) {
                const float rk = row[k];
                const float2 wv = *(const float2*)&W2[k*64 + c];
                c0 = fmaf(rk, wv.x, c0);  c1 = fmaf(rk, wv.y, c1);
            }
            h0 += fmaxf(c0, 0.f);  h1 += fmaxf(c1, 0.f);
            *(float2*)&g_h[r*64 + c] = make_float2(h0, h1);
            __syncwarp();
            row[c] = h0;  row[c+1] = h1;
            __syncwarp();
            float l0 = blv.x, l1 = blv.y, r0 = brv.x, r1 = brv.y;
#pragma unroll
            for (int k = 0; k < 64; k++) {
                const float rk = row[k];
                const float2 wl = *(const float2*)&Wl1[k*64 + c];
                const float2 wr = *(const float2*)&Wr1[k*64 + c];
                l0 = fmaf(rk, wl.x, l0);  l1 = fmaf(rk, wl.y, l1);
                r0 = fmaf(rk, wr.x, r0);  r1 = fmaf(rk, wr.y, r1);
            }
            *(float2*)&g_t1[r*64 + c] = make_float2(l0, l1);
            *(float2*)&g_t2[r*64 + c] = make_float2(r0, r1);
            __syncwarp();
        }
    } else if (bid < 162) {
        // ---------- fold ----------
        const int fb = bid - 160;
        for (int idx = tid; idx < 4096; idx += 256) spool[idx] = We2[idx];
        __syncthreads();
        const int j = tid & 63, il = tid >> 6;
        for (int pass = 0; pass < 8; pass++) {
            const int i = fb*32 + pass*4 + il;
            float sa = 0.f, sb = 0.f;
#pragma unroll
            for (int m = 0; m < 64; m++) {
                const float w2 = spool[m*64 + j];
                sa = fmaf(We1[i*64 + m],      w2, sa);
                sb = fmaf(We1[(64+i)*64 + m], w2, sb);
            }
            g_Wca[i*64 + j] = sa;
            g_Wcb[i*64 + j] = sb;
        }
        if (fb == 0 && tid < 64) {
            float cc = be2[tid];
            for (int m = 0; m < 64; m++) cc = fmaf(be1[m], spool[m*64 + tid], cc);
            g_c2[tid] = cc;
        }
    } else if (bid < 226) {
        // ---------- bucket fill ----------
        for (int e = (bid - 162)*256 + tid; e < E; e += 64*256) {
            const int d = dst[e];
            const int p = atomicAdd(&g_cnt[d], 1);
            if (p < CAP) g_col[d*CAP + p] = src[e];
        }
    } else {
        // ---------- zero 64MB output ----------
        const long ZB = (long)(gridDim.x - 226) * 256;
        float4* o4 = (float4*)out;
        const float4 z4 = make_float4(0.f, 0.f, 0.f, 0.f);
        for (long idx = (long)(bid - 226)*256 + tid; idx < 4194304L; idx += ZB) o4[idx] = z4;
    }
}

// =====================================================================
// K2/K3: GAT (2 warps/node) + residual GEMM + two output GEMMs
// =====================================================================
__global__ void __launch_bounds__(256, 4)
k_gatres(const float* __restrict__ gl, const float* __restrict__ gr,
         const float* __restrict__ att, const float* __restrict__ cb,
         const float* __restrict__ Wres, const float* __restrict__ bres,
         const float* __restrict__ Wo1,  const float* __restrict__ bo1, float* __restrict__ O1,
         const float* __restrict__ Wo2,  const float* __restrict__ bo2, float* __restrict__ O2,
         float* __restrict__ H)
{
    __shared__ float rows[4][64];
    __shared__ float cm[4][32], cden[4][32], cv0[4][32], cv1[4][32];
    const int w = threadIdx.x >> 5, lane = threadIdx.x & 31;
    const int nb = w >> 1;                 // node within block (0..3)
    const int half = w & 1;
    const int i = blockIdx.x*4 + nb;
    const int c = lane*2;

    const float2 av  = *(const float2*)&att[c];
    const float2 grv = *(const float2*)&gr[i*64 + c];

    float m = -3.0e38f, den = 0.f, v0 = 0.f, v1 = 0.f;
    if (half == 0) {
        // self-loop
        const float2 gs = *(const float2*)&gl[i*64 + c];
        float sx = gs.x + grv.x, sy = gs.y + grv.y;
        sx = sx > 0.f ? sx : 0.2f*sx;  sy = sy > 0.f ? sy : 0.2f*sy;
        float e = sx*av.x + sy*av.y;
        e += __shfl_xor_sync(0xffffffffu, e, 1);
        e += __shfl_xor_sync(0xffffffffu, e, 2);
        e += __shfl_xor_sync(0xffffffffu, e, 4);
        m = e;  den = 1.f;  v0 = gs.x;  v1 = gs.y;
    }
    const int cnt  = min(g_cnt[i], CAP);
    const int base = i*CAP;
    const int lo = half ? (cnt >> 1) : 0;
    const int hi = half ? cnt : (cnt >> 1);
    int p = lo;
    for (; p + 2 <= hi; p += 2) {
        const int j0 = g_col[base + p];
        const int j1 = g_col[base + p + 1];
        const float2 ga = *(const float2*)&gl[j0*64 + c];
        const float2 gb = *(const float2*)&gl[j1*64 + c];
        float sx0 = ga.x + grv.x, sy0 = ga.y + grv.y;
        sx0 = sx0 > 0.f ? sx0 : 0.2f*sx0;  sy0 = sy0 > 0.f ? sy0 : 0.2f*sy0;
        float e0 = sx0*av.x + sy0*av.y;
        float tx = gb.x + grv.x, ty = gb.y + grv.y;
        tx = tx > 0.f ? tx : 0.2f*tx;  ty = ty > 0.f ? ty : 0.2f*ty;
        float e1 = tx*av.x + ty*av.y;
        e0 += __shfl_xor_sync(0xffffffffu, e0, 1);
        e1 += __shfl_xor_sync(0xffffffffu, e1, 1);
        e0 += __shfl_xor_sync(0xffffffffu, e0, 2);
        e1 += __shfl_xor_sync(0xffffffffu, e1, 2);
        e0 += __shfl_xor_sync(0xffffffffu, e0, 4);
        e1 += __shfl_xor_sync(0xffffffffu, e1, 4);
        // batched online-softmax update (one rescale per pair)
        const float mn = fmaxf(m, fmaxf(e0, e1));
        const float wM = __expf(m - mn);
        const float w0 = __expf(e0 - mn);
        const float w1 = __expf(e1 - mn);
        den = den*wM + w0 + w1;
        v0  = v0 *wM + w0*ga.x + w1*gb.x;
        v1  = v1 *wM + w0*ga.y + w1*gb.y;
        m = mn;
    }
    if (p < hi) {
        const int j0 = g_col[base + p];
        const float2 ga = *(const float2*)&gl[j0*64 + c];
        float sx0 = ga.x + grv.x, sy0 = ga.y + grv.y;
        sx0 = sx0 > 0.f ? sx0 : 0.2f*sx0;  sy0 = sy0 > 0.f ? sy0 : 0.2f*sy0;
        float e0 = sx0*av.x + sy0*av.y;
        e0 += __shfl_xor_sync(0xffffffffu, e0, 1);
        e0 += __shfl_xor_sync(0xffffffffu, e0, 2);
        e0 += __shfl_xor_sync(0xffffffffu, e0, 4);
        const float mn = fmaxf(m, e0);
        const float wE = __expf(e0 - mn), wM = __expf(m - mn);
        den = den*wM + wE;  v0 = v0*wM + wE*ga.x;  v1 = v1*wM + wE*ga.y;
        m = mn;
    }
    // exchange half-1 partials
    if (half == 1) {
        cm[nb][lane] = m;  cden[nb][lane] = den;
        cv0[nb][lane] = v0;  cv1[nb][lane] = v1;
    }
    __syncthreads();
    if (half == 1) return;

    {
        const float m1 = cm[nb][lane];
        const float mn = fmaxf(m, m1);
        const float wA = __expf(m - mn), wB = __expf(m1 - mn);
        den = den*wA + cden[nb][lane]*wB;
        v0  = v0 *wA + cv0[nb][lane]*wB;
        v1  = v1 *wA + cv1[nb][lane]*wB;
    }
    const float inv = 1.f/den;
    const float2 cbv  = *(const float2*)&cb[c];
    const float2 hold = *(const float2*)&H[i*64 + c];
    float h0 = hold.x + v0*inv + cbv.x;
    float h1 = hold.y + v1*inv + cbv.y;

    float* row = rows[nb];
    row[c] = h0;  row[c+1] = h1;
    __syncwarp();
    {
        const float2 bv = *(const float2*)&bres[c];
        float a0 = bv.x, a1 = bv.y;
#pragma unroll
        for (int k = 0; k < 64; k++) {
            const float rk = row[k];
            const float2 wv = *(const float2*)&Wres[k*64 + c];
            a0 = fmaf(rk, wv.x, a0);  a1 = fmaf(rk, wv.y, a1);
        }
        h0 += fmaxf(a0, 0.f);  h1 += fmaxf(a1, 0.f);
    }
    *(float2*)&H[i*64 + c] = make_float2(h0, h1);
    __syncwarp();
    row[c] = h0;  row[c+1] = h1;
    __syncwarp();
    {
        const float2 b1v = *(const float2*)&bo1[c];
        const float2 b2v = *(const float2*)&bo2[c];
        float a0 = b1v.x, a1 = b1v.y, a2 = b2v.x, a3 = b2v.y;
#pragma unroll
        for (int k = 0; k < 64; k++) {
            const float rk = row[k];
            const float2 w1 = *(const float2*)&Wo1[k*64 + c];
            const float2 w2 = *(const float2*)&Wo2[k*64 + c];
            a0 = fmaf(rk, w1.x, a0);  a1 = fmaf(rk, w1.y, a1);
            a2 = fmaf(rk, w2.x, a2);  a3 = fmaf(rk, w2.y, a3);
        }
        *(float2*)&O1[i*64 + c] = make_float2(a0, a1);
        *(float2*)&O2[i*64 + c] = make_float2(a2, a3);
    }
}

// =====================================================================
// K4: edge MLP — 4 lanes/edge, 8 edges/warp-iter, 2 warps/node
// =====================================================================
__global__ void __launch_bounds__(256, 4)
k_edge(const float* __restrict__ We3, const float* __restrict__ be3, float* __restrict__ out)
{
    const int gw   = blockIdx.x*8 + (threadIdx.x >> 5);   // 8192 warps
    const int lane = threadIdx.x & 31;
    const int i    = gw >> 1;
    const int half = gw & 1;
    const int g = lane >> 2;          // edge group 0..7
    const int q = lane & 3;           // channel quarter: channels q*16..q*16+15

    float4 k0[4], w3[4];
#pragma unroll
    for (int t = 0; t < 4; t++) {
        const int ch = q*16 + t*4;
        w3[t] = *(const float4*)&We3[ch];
        const float4 bv = *(const float4*)&g_B2[i*64 + ch];
        const float4 cc = *(const float4*)&g_c2[ch];
        k0[t] = make_float4(bv.x+cc.x, bv.y+cc.y, bv.z+cc.z, bv.w+cc.w);
    }
    const float b3 = be3[0];
    const int cnt  = min(g_cnt[i], CAP);
    const int base = i*CAP;
    const int lo = half ? (cnt >> 1) : 0;
    const int hi = half ? cnt : (cnt >> 1);
    const int nIter = (hi - lo + 7) >> 3;
    for (int it = 0; it < nIter; it++) {
        const int slot = lo + it*8 + g;
        const bool valid = slot < hi;
        const int s = valid ? g_col[base + slot] : 0;
        float p = 0.f;
#pragma unroll
        for (int t = 0; t < 4; t++) {
            const float4 a = *(const float4*)&g_A2[s*64 + q*16 + t*4];
            p = fmaf(fmaxf(a.x + k0[t].x, 0.f), w3[t].x, p);
            p = fmaf(fmaxf(a.y + k0[t].y, 0.f), w3[t].y, p);
            p = fmaf(fmaxf(a.z + k0[t].z, 0.f), w3[t].z, p);
            p = fmaf(fmaxf(a.w + k0[t].w, 0.f), w3[t].w, p);
        }
        p += __shfl_xor_sync(0xffffffffu, p, 1);
        p += __shfl_xor_sync(0xffffffffu, p, 2);
        if (q == 0 && valid)
            out[(size_t)s*NN + i] = 1.f/(1.f + __expf(-(p + b3)));
    }
}

// ---------------- launch ----------------
extern "C" void kernel_launch(void* const* d_in, const int* in_sizes, int n_in,
                              void* d_out, int out_size)
{
    const float* x    = (const float*)d_in[0];
    const int*   src  = (const int*)  d_in[2];
    const int*   dst  = (const int*)  d_in[3];
    const float* W1   = (const float*)d_in[4];
    const float* b1   = (const float*)d_in[5];
    const float* W2   = (const float*)d_in[6];
    const float* b2   = (const float*)d_in[7];
    const float* Wl1  = (const float*)d_in[8];
    const float* bl1  = (const float*)d_in[9];
    const float* Wr1  = (const float*)d_in[10];
    const float* br1  = (const float*)d_in[11];
    const float* att1 = (const float*)d_in[12];
    const float* cb1  = (const float*)d_in[13];
    const float* W4   = (const float*)d_in[14];
    const float* b4   = (const float*)d_in[15];
    const float* Wl2  = (const float*)d_in[16];
    const float* bl2  = (const float*)d_in[17];
    const float* Wr2  = (const float*)d_in[18];
    const float* br2  = (const float*)d_in[19];
    const float* att2 = (const float*)d_in[20];
    const float* cb2  = (const float*)d_in[21];
    const float* W5   = (const float*)d_in[22];
    const float* b5   = (const float*)d_in[23];
    const float* We1  = (const float*)d_in[24];
    const float* be1  = (const float*)d_in[25];
    const float* We2  = (const float*)d_in[26];
    const float* be2  = (const float*)d_in[27];
    const float* We3  = (const float*)d_in[28];
    const float* be3  = (const float*)d_in[29];
    const int E = in_sizes[2];

    int sms = 148;
    cudaDeviceGetAttribute(&sms, cudaDevAttrMultiProcessorCount, 0);
    const int G1 = sms * 4;

    void* p;
    cudaGetSymbolAddress(&p, g_cnt);
    cudaMemsetAsync(p, 0, NN*sizeof(int), 0);

    float *pt1, *pt2, *pt3, *pt4, *pA2, *pB2, *pWca, *pWcb, *pz, *ph;
    cudaGetSymbolAddress(&p, g_t1);  pt1 = (float*)p;
    cudaGetSymbolAddress(&p, g_t2);  pt2 = (float*)p;
    cudaGetSymbolAddress(&p, g_t3);  pt3 = (float*)p;
    cudaGetSymbolAddress(&p, g_t4);  pt4 = (float*)p;
    cudaGetSymbolAddress(&p, g_A2);  pA2 = (float*)p;
    cudaGetSymbolAddress(&p, g_B2);  pB2 = (float*)p;
    cudaGetSymbolAddress(&p, g_Wca); pWca = (float*)p;
    cudaGetSymbolAddress(&p, g_Wcb); pWcb = (float*)p;
    cudaGetSymbolAddress(&p, g_zero64); pz = (float*)p;
    cudaGetSymbolAddress(&p, g_h);   ph = (float*)p;

    k_prep<<<G1, 256>>>(x, src, dst, W1, b1, W2, b2, Wl1, bl1, Wr1, br1,
                        We1, be1, We2, be2, (float*)d_out, E);

    k_gatres<<<1024, 256>>>(pt1, pt2, att1, cb1, W4, b4,
                            Wl2, bl2, pt3,  Wr2, br2, pt4,  ph);

    k_gatres<<<1024, 256>>>(pt3, pt4, att2, cb2, W5, b5,
                            pWca, pz, pA2,  pWcb, pz, pB2,  ph);

    k_edge<<<1024, 256>>>(We3, be3, (float*)d_out);
}

// round 6
// speedup vs baseline: 1.5584x; 1.2604x over previous
#include <cuda_runtime.h>
#include <cuda_bf16.h>
#include <cstddef>

#define NN 4096
#define CAP 192

// ---------------- device scratch ----------------
__device__ float g_h [NN*64];
__device__ float g_t1[NN*64];
__device__ float g_t2[NN*64];
__device__ float g_A2[NN*64];
__device__ float g_B2[NN*64];
__device__ float g_Wca[64*64];
__device__ float g_Wcb[64*64];
__device__ float g_c2[64];
__device__ int   g_cnt[NN];
__device__ int   g_col[NN*CAP];

// =====================================================================
// K1: encoder (block-coop, reg weights) | We-fold | bucket fill
// =====================================================================
__global__ void __launch_bounds__(256)
k_prep(const float* __restrict__ x, const int* __restrict__ src, const int* __restrict__ dst,
       const float* __restrict__ W1,  const float* __restrict__ b1,
       const float* __restrict__ W2,  const float* __restrict__ b2,
       const float* __restrict__ We1, const float* __restrict__ be1,
       const float* __restrict__ We2, const float* __restrict__ be2,
       int E)
{
    __shared__ float spool[4096];
    __shared__ float xs[4][16];
    __shared__ float hs[4][64];
    const int bid = blockIdx.x, tid = threadIdx.x;

    if (bid < 256) {
        // ---- encoder: h = relu(xW1+b1); h += relu(hW2+b2); 16 rows/block ----
        const int j = tid & 63, rg = tid >> 6;
        float w1[16], w2[64];
#pragma unroll
        for (int k = 0; k < 16; k++) w1[k] = W1[k*64 + j];
#pragma unroll
        for (int k = 0; k < 64; k++) w2[k] = W2[k*64 + j];
        const float b1j = b1[j], b2j = b2[j];
        for (int r = 0; r < 4; r++) {
            const int row = bid*16 + r*4 + rg;
            __syncthreads();
            if (j < 16) xs[rg][j] = x[row*16 + j];
            __syncthreads();
            float acc = b1j;
#pragma unroll
            for (int k = 0; k < 16; k++) acc = fmaf(xs[rg][k], w1[k], acc);
            const float h1 = fmaxf(acc, 0.f);
            hs[rg][j] = h1;
            __syncthreads();
            float acc2 = b2j;
#pragma unroll
            for (int k = 0; k < 64; k++) acc2 = fmaf(hs[rg][k], w2[k], acc2);
            g_h[row*64 + j] = h1 + fmaxf(acc2, 0.f);
        }
    } else if (bid < 258) {
        // ---- fold: Wca=We1[:64]@We2, Wcb=We1[64:]@We2, c2=be1@We2+be2 ----
        const int fb = bid - 256;
        for (int idx = tid; idx < 4096; idx += 256) spool[idx] = We2[idx];
        __syncthreads();
        const int j = tid & 63, il = tid >> 6;
        for (int pass = 0; pass < 8; pass++) {
            const int i = fb*32 + pass*4 + il;
            float sa = 0.f, sb = 0.f;
#pragma unroll
            for (int m = 0; m < 64; m++) {
                const float w2v = spool[m*64 + j];
                sa = fmaf(We1[i*64 + m],      w2v, sa);
                sb = fmaf(We1[(64+i)*64 + m], w2v, sb);
            }
            g_Wca[i*64 + j] = sa;
            g_Wcb[i*64 + j] = sb;
        }
        if (fb == 0 && tid < 64) {
            float cc = be2[tid];
            for (int m = 0; m < 64; m++) cc = fmaf(be1[m], spool[m*64 + tid], cc);
            g_c2[tid] = cc;
        }
    } else {
        // ---- bucket fill (g_cnt pre-zeroed; self-loops implicit) ----
        for (int e = (bid - 258)*256 + tid; e < E; e += 64*256) {
            const int d = dst[e];
            const int p = atomicAdd(&g_cnt[d], 1);
            if (p < CAP) g_col[d*CAP + p] = src[e];
        }
    }
}

// =====================================================================
// dual GEMM: Ya = X@Wa+ba, Yb = X@Wb+bb (512 threads, reg weights)
// =====================================================================
__global__ void __launch_bounds__(512)
k_gemm_dual(const float* __restrict__ X,
            const float* __restrict__ Wa, const float* __restrict__ ba,
            const float* __restrict__ Wb, const float* __restrict__ bb,
            float* __restrict__ Ya, float* __restrict__ Yb)
{
    const int grp = threadIdx.x >> 8;
    const int j   = threadIdx.x & 63;
    const int rg  = (threadIdx.x >> 6) & 3;
    __shared__ float xs[4][64];
    const float* W = grp ? Wb : Wa;
    const float* B = grp ? bb : ba;
    float*       Y = grp ? Yb : Ya;
    float w[64];
#pragma unroll
    for (int k = 0; k < 64; k++) w[k] = W[k*64 + j];
    const float b = B ? B[j] : 0.f;
    for (int r = 0; r < 4; r++) {
        const int row = blockIdx.x*16 + r*4 + rg;
        __syncthreads();
        if (grp == 0) xs[rg][j] = X[row*64 + j];
        __syncthreads();
        float acc = b;
#pragma unroll
        for (int k = 0; k < 64; k++) acc = fmaf(xs[rg][k], w[k], acc);
        Y[row*64 + j] = acc;
    }
}

// =====================================================================
// residual GEMM: H = H + relu(H@W + b)
// =====================================================================
__global__ void __launch_bounds__(256)
k_gemm_res(float* __restrict__ H, const float* __restrict__ W,
           const float* __restrict__ bias)
{
    const int j  = threadIdx.x & 63;
    const int rg = threadIdx.x >> 6;
    __shared__ float xs[4][64];
    float w[64];
#pragma unroll
    for (int k = 0; k < 64; k++) w[k] = W[k*64 + j];
    const float b = bias[j];
    for (int r = 0; r < 4; r++) {
        const int row = blockIdx.x*16 + r*4 + rg;
        __syncthreads();
        xs[rg][j] = H[row*64 + j];
        __syncthreads();
        float acc = b;
#pragma unroll
        for (int k = 0; k < 64; k++) acc = fmaf(xs[rg][k], w[k], acc);
        H[row*64 + j] = xs[rg][j] + fmaxf(acc, 0.f);
    }
}

// =====================================================================
// GAT attention only: 2 warps/node, unroll-4 scores, online softmax
// =====================================================================
__global__ void __launch_bounds__(256)
k_gat(const float* __restrict__ gl, const float* __restrict__ gr,
      const float* __restrict__ att, const float* __restrict__ cb,
      float* __restrict__ H)
{
    __shared__ float cm[4][32], cden[4][32], cv0[4][32], cv1[4][32];
    const int w = threadIdx.x >> 5, lane = threadIdx.x & 31;
    const int nb = w >> 1, half = w & 1;
    const int i = blockIdx.x*4 + nb;
    const int c = lane*2;

    const float2 av  = *(const float2*)&att[c];
    const float2 grv = *(const float2*)&gr[i*64 + c];

    float m = -3.0e38f, den = 0.f, v0 = 0.f, v1 = 0.f;
    if (half == 0) {
        const float2 gs = *(const float2*)&gl[i*64 + c];
        float sx = gs.x + grv.x, sy = gs.y + grv.y;
        sx = sx > 0.f ? sx : 0.2f*sx;  sy = sy > 0.f ? sy : 0.2f*sy;
        float e = sx*av.x + sy*av.y;
        e += __shfl_xor_sync(0xffffffffu, e, 1);
        e += __shfl_xor_sync(0xffffffffu, e, 2);
        e += __shfl_xor_sync(0xffffffffu, e, 4);
        m = e;  den = 1.f;  v0 = gs.x;  v1 = gs.y;
    }
    const int cnt  = min(g_cnt[i], CAP);
    const int base = i*CAP;
    const int lo = half ? (cnt >> 1) : 0;
    const int hi = half ? cnt : (cnt >> 1);
    int p = lo;
    for (; p + 4 <= hi; p += 4) {
        const int j0 = g_col[base + p];
        const int j1 = g_col[base + p + 1];
        const int j2 = g_col[base + p + 2];
        const int j3 = g_col[base + p + 3];
        const float2 ga = *(const float2*)&gl[j0*64 + c];
        const float2 gb = *(const float2*)&gl[j1*64 + c];
        const float2 gc = *(const float2*)&gl[j2*64 + c];
        const float2 gd = *(const float2*)&gl[j3*64 + c];
        float e0, e1, e2, e3;
        {
            float ax = ga.x+grv.x, ay = ga.y+grv.y;
            ax = ax>0.f?ax:0.2f*ax;  ay = ay>0.f?ay:0.2f*ay;
            e0 = ax*av.x + ay*av.y;
            float bx = gb.x+grv.x, by = gb.y+grv.y;
            bx = bx>0.f?bx:0.2f*bx;  by = by>0.f?by:0.2f*by;
            e1 = bx*av.x + by*av.y;
            float cx = gc.x+grv.x, cy = gc.y+grv.y;
            cx = cx>0.f?cx:0.2f*cx;  cy = cy>0.f?cy:0.2f*cy;
            e2 = cx*av.x + cy*av.y;
            float dx = gd.x+grv.x, dy = gd.y+grv.y;
            dx = dx>0.f?dx:0.2f*dx;  dy = dy>0.f?dy:0.2f*dy;
            e3 = dx*av.x + dy*av.y;
        }
        e0 += __shfl_xor_sync(0xffffffffu, e0, 1);
        e1 += __shfl_xor_sync(0xffffffffu, e1, 1);
        e2 += __shfl_xor_sync(0xffffffffu, e2, 1);
        e3 += __shfl_xor_sync(0xffffffffu, e3, 1);
        e0 += __shfl_xor_sync(0xffffffffu, e0, 2);
        e1 += __shfl_xor_sync(0xffffffffu, e1, 2);
        e2 += __shfl_xor_sync(0xffffffffu, e2, 2);
        e3 += __shfl_xor_sync(0xffffffffu, e3, 2);
        e0 += __shfl_xor_sync(0xffffffffu, e0, 4);
        e1 += __shfl_xor_sync(0xffffffffu, e1, 4);
        e2 += __shfl_xor_sync(0xffffffffu, e2, 4);
        e3 += __shfl_xor_sync(0xffffffffu, e3, 4);
        const float mn = fmaxf(fmaxf(m, fmaxf(e0, e1)), fmaxf(e2, e3));
        const float wM = __expf(m - mn);
        const float w0 = __expf(e0 - mn);
        const float w1 = __expf(e1 - mn);
        const float w2 = __expf(e2 - mn);
        const float w3 = __expf(e3 - mn);
        den = den*wM + (w0 + w1) + (w2 + w3);
        v0  = v0 *wM + (w0*ga.x + w1*gb.x) + (w2*gc.x + w3*gd.x);
        v1  = v1 *wM + (w0*ga.y + w1*gb.y) + (w2*gc.y + w3*gd.y);
        m = mn;
    }
    for (; p < hi; p++) {
        const int j0 = g_col[base + p];
        const float2 ga = *(const float2*)&gl[j0*64 + c];
        float sx0 = ga.x + grv.x, sy0 = ga.y + grv.y;
        sx0 = sx0 > 0.f ? sx0 : 0.2f*sx0;  sy0 = sy0 > 0.f ? sy0 : 0.2f*sy0;
        float e0 = sx0*av.x + sy0*av.y;
        e0 += __shfl_xor_sync(0xffffffffu, e0, 1);
        e0 += __shfl_xor_sync(0xffffffffu, e0, 2);
        e0 += __shfl_xor_sync(0xffffffffu, e0, 4);
        const float mn = fmaxf(m, e0);
        const float wE = __expf(e0 - mn), wM = __expf(m - mn);
        den = den*wM + wE;  v0 = v0*wM + wE*ga.x;  v1 = v1*wM + wE*ga.y;
        m = mn;
    }
    if (half == 1) {
        cm[nb][lane] = m;  cden[nb][lane] = den;
        cv0[nb][lane] = v0;  cv1[nb][lane] = v1;
    }
    __syncthreads();
    if (half == 1) return;
    {
        const float m1 = cm[nb][lane];
        const float mn = fmaxf(m, m1);
        const float wA = __expf(m - mn), wB = __expf(m1 - mn);
        den = den*wA + cden[nb][lane]*wB;
        v0  = v0 *wA + cv0[nb][lane]*wB;
        v1  = v1 *wA + cv1[nb][lane]*wB;
    }
    const float inv = 1.f/den;
    const float2 cbv = *(const float2*)&cb[c];
    float2* hp = (float2*)&H[i*64 + c];
    float2 hv = *hp;
    hv.x += v0*inv + cbv.x;
    hv.y += v1*inv + cbv.y;
    *hp = hv;
}

// =====================================================================
// edge MLP: 16 lanes/edge (coalesced 256B row loads), 4 warps/node
// =====================================================================
__global__ void __launch_bounds__(256)
k_edge(const float* __restrict__ We3, const float* __restrict__ be3, float* __restrict__ out)
{
    const int gw   = blockIdx.x*8 + (threadIdx.x >> 5);   // 16384 warps
    const int lane = threadIdx.x & 31;
    const int i    = gw >> 2;
    const int q    = gw & 3;
    const int sub  = lane >> 4;       // 0/1: which edge of the pair
    const int t    = lane & 15;       // channel slice: t*4..t*4+3
    const int ch   = t*4;

    const float4 w3 = *(const float4*)&We3[ch];
    const float4 bv = *(const float4*)&g_B2[i*64 + ch];
    const float4 cc = *(const float4*)&g_c2[ch];
    const float4 k0 = make_float4(bv.x+cc.x, bv.y+cc.y, bv.z+cc.z, bv.w+cc.w);
    const float  b3 = be3[0];

    const int cnt  = min(g_cnt[i], CAP);
    const int base = i*CAP;
    const int lo = (cnt*q) >> 2;
    const int hi = (cnt*(q+1)) >> 2;

    for (int sb = lo; sb < hi; sb += 4) {     // 2 pairs per iter (4 edges)
        const int slotA = sb + sub;
        const int slotB = sb + 2 + sub;
        const bool vA = slotA < hi;
        const bool vB = slotB < hi;
        const int sA = vA ? g_col[base + slotA] : 0;
        const int sB = vB ? g_col[base + slotB] : 0;
        const float4 aA = *(const float4*)&g_A2[sA*64 + ch];
        const float4 aB = *(const float4*)&g_A2[sB*64 + ch];
        float pA = fmaxf(aA.x + k0.x, 0.f)*w3.x;
        pA = fmaf(fmaxf(aA.y + k0.y, 0.f), w3.y, pA);
        pA = fmaf(fmaxf(aA.z + k0.z, 0.f), w3.z, pA);
        pA = fmaf(fmaxf(aA.w + k0.w, 0.f), w3.w, pA);
        float pB = fmaxf(aB.x + k0.x, 0.f)*w3.x;
        pB = fmaf(fmaxf(aB.y + k0.y, 0.f), w3.y, pB);
        pB = fmaf(fmaxf(aB.z + k0.z, 0.f), w3.z, pB);
        pB = fmaf(fmaxf(aB.w + k0.w, 0.f), w3.w, pB);
#pragma unroll
        for (int off = 1; off <= 8; off <<= 1) {
            pA += __shfl_xor_sync(0xffffffffu, pA, off);
            pB += __shfl_xor_sync(0xffffffffu, pB, off);
        }
        if (t == 0) {
            if (vA) out[(size_t)sA*NN + i] = 1.f/(1.f + __expf(-(pA + b3)));
            if (vB) out[(size_t)sB*NN + i] = 1.f/(1.f + __expf(-(pB + b3)));
        }
    }
}

// ---------------- launch ----------------
extern "C" void kernel_launch(void* const* d_in, const int* in_sizes, int n_in,
                              void* d_out, int out_size)
{
    const float* x    = (const float*)d_in[0];
    const int*   src  = (const int*)  d_in[2];
    const int*   dst  = (const int*)  d_in[3];
    const float* W1   = (const float*)d_in[4];
    const float* b1   = (const float*)d_in[5];
    const float* W2   = (const float*)d_in[6];
    const float* b2   = (const float*)d_in[7];
    const float* Wl1  = (const float*)d_in[8];
    const float* bl1  = (const float*)d_in[9];
    const float* Wr1  = (const float*)d_in[10];
    const float* br1  = (const float*)d_in[11];
    const float* att1 = (const float*)d_in[12];
    const float* cb1  = (const float*)d_in[13];
    const float* W4   = (const float*)d_in[14];
    const float* b4   = (const float*)d_in[15];
    const float* Wl2  = (const float*)d_in[16];
    const float* bl2  = (const float*)d_in[17];
    const float* Wr2  = (const float*)d_in[18];
    const float* br2  = (const float*)d_in[19];
    const float* att2 = (const float*)d_in[20];
    const float* cb2  = (const float*)d_in[21];
    const float* W5   = (const float*)d_in[22];
    const float* b5   = (const float*)d_in[23];
    const float* We1  = (const float*)d_in[24];
    const float* be1  = (const float*)d_in[25];
    const float* We2  = (const float*)d_in[26];
    const float* be2  = (const float*)d_in[27];
    const float* We3  = (const float*)d_in[28];
    const float* be3  = (const float*)d_in[29];
    const int E = in_sizes[2];

    void* p;
    float *pt1, *pt2, *pA2, *pB2, *pWca, *pWcb, *ph;
    cudaGetSymbolAddress(&p, g_t1);  pt1 = (float*)p;
    cudaGetSymbolAddress(&p, g_t2);  pt2 = (float*)p;
    cudaGetSymbolAddress(&p, g_A2);  pA2 = (float*)p;
    cudaGetSymbolAddress(&p, g_B2);  pB2 = (float*)p;
    cudaGetSymbolAddress(&p, g_Wca); pWca = (float*)p;
    cudaGetSymbolAddress(&p, g_Wcb); pWcb = (float*)p;
    cudaGetSymbolAddress(&p, g_h);   ph = (float*)p;

    cudaGetSymbolAddress(&p, g_cnt);
    cudaMemsetAsync(p, 0, NN*sizeof(int), 0);

    // fork: zero the 64MB output on a parallel capture branch
    cudaStream_t s2 = 0;
    cudaEvent_t evF = 0, evJ = 0;
    bool forked = false;
    if (cudaStreamCreateWithFlags(&s2, cudaStreamNonBlocking) == cudaSuccess &&
        cudaEventCreateWithFlags(&evF, cudaEventDisableTiming) == cudaSuccess &&
        cudaEventCreateWithFlags(&evJ, cudaEventDisableTiming) == cudaSuccess) {
        cudaEventRecord(evF, 0);
        cudaStreamWaitEvent(s2, evF, 0);
        cudaMemsetAsync(d_out, 0, (size_t)out_size * sizeof(float), s2);
        cudaEventRecord(evJ, s2);
        forked = true;
    } else {
        cudaMemsetAsync(d_out, 0, (size_t)out_size * sizeof(float), 0);
    }

    k_prep<<<322, 256>>>(x, src, dst, W1, b1, W2, b2, We1, be1, We2, be2, E);

    k_gemm_dual<<<256, 512>>>(ph, Wl1, bl1, Wr1, br1, pt1, pt2);
    k_gat<<<1024, 256>>>(pt1, pt2, att1, cb1, ph);
    k_gemm_res<<<256, 256>>>(ph, W4, b4);

    k_gemm_dual<<<256, 512>>>(ph, Wl2, bl2, Wr2, br2, pt1, pt2);
    k_gat<<<1024, 256>>>(pt1, pt2, att2, cb2, ph);
    k_gemm_res<<<256, 256>>>(ph, W5, b5);

    k_gemm_dual<<<256, 512>>>(ph, pWca, nullptr, pWcb, nullptr, pA2, pB2);

    if (forked) cudaStreamWaitEvent(0, evJ, 0);
    k_edge<<<2048, 256>>>(We3, be3, (float*)d_out);
}